// round 10
// baseline (speedup 1.0000x reference)
#include <cuda_runtime.h>
#include <cstdint>

#define D    128
#define C    21
#define PROW 32       // padded P-table row (floats) = one 128B line
#define MAXN 50000
#define NPT  8        // nodes per warp in nodeproj
#define CP   132

typedef unsigned long long ull;

// Scratch (static device globals — no allocation allowed)
__device__ float g_WsT[C * CP];
__device__ float g_WdT[C * CP];
__device__ float g_bc[C];
__device__ float g_Ps [MAXN * PROW];   // normal rows: float i = P[i]
__device__ float g_Pd [MAXN * PROW];
__device__ float g_PsR[MAXN * PROW];   // rotated: float j = P[j+1] (j=0..19), float20 = P[0]
__device__ float g_PdR[MAXN * PROW];
__device__ int   g_is64;

// ---- packed fp32x2 ops (sm_103a; PTX-only forms) ---------------------------
__device__ __forceinline__ ull fma2(ull a, ull b, ull c) {
    ull d;
    asm("fma.rn.f32x2 %0, %1, %2, %3;" : "=l"(d) : "l"(a), "l"(b), "l"(c));
    return d;
}
__device__ __forceinline__ ull add2(ull a, ull b) {
    ull d;
    asm("add.rn.f32x2 %0, %1, %2;" : "=l"(d) : "l"(a), "l"(b));
    return d;
}
__device__ __forceinline__ void unpack2(ull v, float& lo, float& hi) {
    uint32_t l, h;
    asm("mov.b64 {%0, %1}, %2;" : "=r"(l), "=r"(h) : "l"(v));
    lo = __uint_as_float(l); hi = __uint_as_float(h);
}
__device__ __forceinline__ float f2lo(ull v) {
    float lo, hi; unpack2(v, lo, hi); return lo;
}
__device__ __forceinline__ float f2sum(ull v) {
    float lo, hi; unpack2(v, lo, hi); return lo + hi;
}

// ---------------------------------------------------------------------------
// combine_kernel: no smem/sync. 8 lanes per output, shfl-tree reduce.
// Last block: dtype detection + bias fold.
// ---------------------------------------------------------------------------
__global__ void __launch_bounds__(256) combine_kernel(const float* __restrict__ Wsrc,
                                                      const float* __restrict__ Wdst,
                                                      const float* __restrict__ Wcls,
                                                      const float* __restrict__ bfuse,
                                                      const float* __restrict__ bcls,
                                                      const uint32_t* __restrict__ ew) {
    if (blockIdx.x == gridDim.x - 1) {
        if (threadIdx.x < 32) {
            int lane = threadIdx.x;
            uint32_t v = 0;
#pragma unroll
            for (int i = 0; i < 8; i++)
                v |= ew[1 + 2 * (lane + 32 * i)];   // odd words: int64 high halves
#pragma unroll
            for (int o = 16; o; o >>= 1)
                v |= __shfl_xor_sync(0xffffffffu, v, o);
            if (lane == 0) g_is64 = (v == 0u) ? 1 : 0;
        } else if (threadIdx.x < 32 + C) {
            int c = threadIdx.x - 32;
            float acc = bcls[c];
#pragma unroll 8
            for (int j = 0; j < D; j++)
                acc = fmaf(__ldg(&bfuse[j]), __ldg(&Wcls[j * C + c]), acc);
            g_bc[c] = acc;
        }
        return;
    }

    int t = blockIdx.x * blockDim.x + threadIdx.x;
    int o = t >> 3;                                  // output id in [0, 2*D*C)
    int p = t & 7;                                   // eighth of K (16 elems)
    int m = o / (D * C);
    int r = o % (D * C);
    int k = r / C;
    int c = r % C;

    const float4* W4 = (const float4*)((m ? Wdst : Wsrc) + (size_t)k * D) + 4 * p;
    float acc = 0.f;
#pragma unroll
    for (int j = 0; j < 4; j++) {
        float4 w = __ldg(W4 + j);
        int e = 16 * p + 4 * j;
        acc = fmaf(w.x, __ldg(&Wcls[(e + 0) * C + c]), acc);
        acc = fmaf(w.y, __ldg(&Wcls[(e + 1) * C + c]), acc);
        acc = fmaf(w.z, __ldg(&Wcls[(e + 2) * C + c]), acc);
        acc = fmaf(w.w, __ldg(&Wcls[(e + 3) * C + c]), acc);
    }
    acc += __shfl_down_sync(0xffffffffu, acc, 4);
    acc += __shfl_down_sync(0xffffffffu, acc, 2);
    acc += __shfl_down_sync(0xffffffffu, acc, 1);
    if (p == 0)
        (m ? g_WdT : g_WsT)[c * CP + k] = acc;
}

// ---------------------------------------------------------------------------
// Per-node projection: warp = NPT nodes x (lane = class), f32x2 FMAs.
// Writes both normal and rotated table rows.
// ---------------------------------------------------------------------------
__global__ void __launch_bounds__(256) nodeproj_kernel(const float* __restrict__ emb, int N) {
    __shared__ __align__(16) float sWs[C * CP];
    __shared__ __align__(16) float sWd[C * CP];
    __shared__ float sbc[C];
    for (int i = threadIdx.x; i < C * CP; i += blockDim.x) {
        sWs[i] = g_WsT[i];
        sWd[i] = g_WdT[i];
    }
    if (threadIdx.x < C) sbc[threadIdx.x] = g_bc[threadIdx.x];
    __syncthreads();

    int wid  = threadIdx.x >> 5;
    int lane = threadIdx.x & 31;
    int n0   = (blockIdx.x * 8 + wid) * NPT;
    if (n0 >= N) return;

    int cc = (lane < C) ? lane : (C - 1);
    const ulonglong2* ws2 = (const ulonglong2*)(sWs + cc * CP);
    const ulonglong2* wd2 = (const ulonglong2*)(sWd + cc * CP);
    const ulonglong2* e2  = (const ulonglong2*)(emb + (size_t)n0 * D);

    ull as2[NPT], ad2[NPT];
#pragma unroll
    for (int j = 0; j < NPT; j++) { as2[j] = 0ull; ad2[j] = 0ull; }

    int nv = N - n0; if (nv > NPT) nv = NPT;

    if (nv == NPT) {
#pragma unroll
        for (int k = 0; k < D / 4; k++) {
            ulonglong2 ws = ws2[k];
            ulonglong2 wd = wd2[k];
#pragma unroll
            for (int j = 0; j < NPT; j++) {
                ulonglong2 ev = __ldg(e2 + (size_t)j * (D / 4) + k);  // warp broadcast
                as2[j] = fma2(ev.x, ws.x, as2[j]);
                as2[j] = fma2(ev.y, ws.y, as2[j]);
                ad2[j] = fma2(ev.x, wd.x, ad2[j]);
                ad2[j] = fma2(ev.y, wd.y, ad2[j]);
            }
        }
    } else {
        for (int k = 0; k < D / 4; k++) {
            ulonglong2 ws = ws2[k];
            ulonglong2 wd = wd2[k];
            for (int j = 0; j < nv; j++) {
                ulonglong2 ev = __ldg(e2 + (size_t)j * (D / 4) + k);
                as2[j] = fma2(ev.x, ws.x, as2[j]);
                as2[j] = fma2(ev.y, ws.y, as2[j]);
                ad2[j] = fma2(ev.x, wd.x, ad2[j]);
                ad2[j] = fma2(ev.y, wd.y, ad2[j]);
            }
        }
    }

    if (lane < C) {
        float bc = sbc[lane];
        int pos = (lane == 0) ? 20 : (lane - 1);   // rotated-row position of class `lane`
#pragma unroll
        for (int j = 0; j < NPT; j++) {
            if (j < nv) {
                size_t row = (size_t)(n0 + j) * PROW;
                float vs = f2sum(as2[j]) + bc;
                float vd = f2sum(ad2[j]);
                g_Ps [row + lane] = vs;
                g_Pd [row + lane] = vd;
                g_PsR[row + pos]  = vs;
                g_PdR[row + pos]  = vd;
            }
        }
    }
}

// ---------------------------------------------------------------------------
// Edge kernel: quarter-warp LDG.128 gathers + rotation-aligned STG.64 stores.
// Warp owns 32 edges; 8 iterations of 4 edges. Lane (g=lane>>3, q8=lane&7):
//  - 2 shfls give (s,d) of edge 4it+g
//  - predicated LDG.128 (q8<=5): even g reads normal rows, odd g rotated rows
//    (so every lane's two float-pairs are 8B-aligned in the output)
//  - 2 packed f32x2 adds
//  - q8<=4: two STG.64 (contiguous 336B block); q8==5: straggler STG.32
// MIO per 32 edges: 8 x (2 SHFL + 2 LDG + 3 STG) = 56 (vs 96 in R6), stores
// stay contiguous (the R8 scatter mistake is avoided).
// ---------------------------------------------------------------------------
__global__ void __launch_bounds__(256) edge_kernel(const uint32_t* __restrict__ ew,
                                                   float* __restrict__ out,
                                                   uint32_t E) {
    const uint32_t F = 0xffffffffu;
    uint32_t wid  = threadIdx.x >> 5;
    uint32_t lane = threadIdx.x & 31;
    uint32_t warp = blockIdx.x * 8u + wid;
    uint32_t e0   = warp * 32u;
    if (e0 >= E) return;

    uint32_t myE = e0 + lane;
    bool have = (myE < E);
    uint32_t sv = 0, dv = 0;
    if (g_is64) {
        const uint2* ew2 = (const uint2*)ew;
        if (have) {
            sv = ew2[myE].x;
            dv = ew2[(size_t)E + myE].x;
        }
    } else {
        if (have) {
            sv = ew[myE];
            dv = ew[(size_t)E + myE];
        }
    }

    uint32_t nIt = E - e0; if (nIt > 32u) nIt = 32u;

    if (nIt == 32u) {
        uint32_t g   = lane >> 3;        // group 0..3 -> edge 4it+g
        uint32_t q8  = lane & 7u;        // 16B chunk within row
        uint32_t par = g & 1u;           // odd edges use rotated tables
        const ulonglong2* TS = par ? (const ulonglong2*)g_PsR : (const ulonglong2*)g_Ps;
        const ulonglong2* TD = par ? (const ulonglong2*)g_PdR : (const ulonglong2*)g_Pd;
        bool doLoad = (q8 <= 5u);
        bool wide   = (q8 <= 4u);
        bool strag  = (q8 == 5u);
        uint32_t soff   = 84u * g + (par ? 4u : 0u) + 16u * q8;   // wide-store base
        uint32_t stroff = 84u * g + (par ? 0u : 80u);             // straggler byte
        char* wbase = (char*)(out + (size_t)e0 * C);              // 2688B-aligned

#pragma unroll
        for (uint32_t it = 0; it < 8u; ++it) {
            uint32_t eidx = 4u * it + g;
            uint32_t s = __shfl_sync(F, sv, eidx);
            uint32_t d = __shfl_sync(F, dv, eidx);
            ull v0 = 0, v1 = 0;
            if (doLoad) {
                ulonglong2 a = __ldg(TS + (size_t)s * 8u + q8);   // row = 8 x 16B
                ulonglong2 b = __ldg(TD + (size_t)d * 8u + q8);
                v0 = add2(a.x, b.x);
                v1 = add2(a.y, b.y);
            }
            char* p = wbase + 336u * it;
            if (wide) {
                __stcs((ull*)(p + soff),      v0);
                __stcs((ull*)(p + soff + 8u), v1);
            }
            if (strag)
                __stcs((float*)(p + stroff), f2lo(v0));
        }
    } else {
        const float* __restrict__ Ps = g_Ps;
        const float* __restrict__ Pd = g_Pd;
        for (uint32_t it = 0; it < nIt; ++it) {
            uint32_t s = __shfl_sync(F, sv, it);
            uint32_t d = __shfl_sync(F, dv, it);
            if (lane < C) {
                float v = __ldg(&Ps[(size_t)s * PROW + lane]) +
                          __ldg(&Pd[(size_t)d * PROW + lane]);
                out[(size_t)(e0 + it) * C + lane] = v;
            }
        }
    }
}

// ---------------------------------------------------------------------------
extern "C" void kernel_launch(void* const* d_in, const int* in_sizes, int n_in,
                              void* d_out, int out_size) {
    const float*    emb   = (const float*)d_in[0];
    const uint32_t* ei    = (const uint32_t*)d_in[1];
    const float*    Wsrc  = (const float*)d_in[2];
    const float*    Wdst  = (const float*)d_in[3];
    const float*    bfuse = (const float*)d_in[4];
    const float*    Wcls  = (const float*)d_in[5];
    const float*    bcls  = (const float*)d_in[6];
    float* out = (float*)d_out;

    int N = in_sizes[0] / D;          // 50000
    int E = in_sizes[1] / 2;          // 1600000

    int cblocks = (2 * D * C * 8) / 256 + 1;   // 168 compute + 1 detect/bias
    combine_kernel<<<cblocks, 256>>>(Wsrc, Wdst, Wcls, bfuse, bcls, ei);

    int nodesPerBlock = 8 * NPT;
    nodeproj_kernel<<<(N + nodesPerBlock - 1) / nodesPerBlock, 256>>>(emb, N);

    uint32_t warps  = ((uint32_t)E + 31u) / 32u;
    uint32_t blocks = (warps + 7u) / 8u;
    edge_kernel<<<blocks, 256>>>(ei, out, (uint32_t)E);
}

// round 11
// speedup vs baseline: 1.0688x; 1.0688x over previous
#include <cuda_runtime.h>
#include <cstdint>

#define D    128
#define C    21
#define PROW 32       // padded P-table row (floats) = one 128B line
#define MAXN 50000
#define NPT  8        // nodes per warp in nodeproj
#define CP   132

typedef unsigned long long ull;

// Scratch (static device globals — no allocation allowed)
__device__ float g_WsT[C * CP];
__device__ float g_WdT[C * CP];
__device__ float g_bc[C];
__device__ float g_Ps[MAXN * PROW];
__device__ float g_Pd[MAXN * PROW];
__device__ int   g_is64;

// ---- packed fp32x2 ops (sm_103a; PTX-only forms) ---------------------------
__device__ __forceinline__ ull fma2(ull a, ull b, ull c) {
    ull d;
    asm("fma.rn.f32x2 %0, %1, %2, %3;" : "=l"(d) : "l"(a), "l"(b), "l"(c));
    return d;
}
__device__ __forceinline__ ull add2(ull a, ull b) {
    ull d;
    asm("add.rn.f32x2 %0, %1, %2;" : "=l"(d) : "l"(a), "l"(b));
    return d;
}
__device__ __forceinline__ void unpack2(ull v, float& lo, float& hi) {
    uint32_t l, h;
    asm("mov.b64 {%0, %1}, %2;" : "=r"(l), "=r"(h) : "l"(v));
    lo = __uint_as_float(l); hi = __uint_as_float(h);
}
__device__ __forceinline__ float f2sum(ull v) {
    float lo, hi; unpack2(v, lo, hi); return lo + hi;
}

// ---------------------------------------------------------------------------
// combine_kernel: no smem/sync. 8 lanes per output, shfl-tree reduce.
// Last block: dtype detection + bias fold.
// ---------------------------------------------------------------------------
__global__ void __launch_bounds__(256) combine_kernel(const float* __restrict__ Wsrc,
                                                      const float* __restrict__ Wdst,
                                                      const float* __restrict__ Wcls,
                                                      const float* __restrict__ bfuse,
                                                      const float* __restrict__ bcls,
                                                      const uint32_t* __restrict__ ew) {
    if (blockIdx.x == gridDim.x - 1) {
        if (threadIdx.x < 32) {
            int lane = threadIdx.x;
            uint32_t v = 0;
#pragma unroll
            for (int i = 0; i < 8; i++)
                v |= ew[1 + 2 * (lane + 32 * i)];   // odd words: int64 high halves
#pragma unroll
            for (int o = 16; o; o >>= 1)
                v |= __shfl_xor_sync(0xffffffffu, v, o);
            if (lane == 0) g_is64 = (v == 0u) ? 1 : 0;
        } else if (threadIdx.x < 32 + C) {
            int c = threadIdx.x - 32;
            float acc = bcls[c];
#pragma unroll 8
            for (int j = 0; j < D; j++)
                acc = fmaf(__ldg(&bfuse[j]), __ldg(&Wcls[j * C + c]), acc);
            g_bc[c] = acc;
        }
        return;
    }

    int t = blockIdx.x * blockDim.x + threadIdx.x;
    int o = t >> 3;                                  // output id in [0, 2*D*C)
    int p = t & 7;                                   // eighth of K (16 elems)
    int m = o / (D * C);
    int r = o % (D * C);
    int k = r / C;
    int c = r % C;

    const float4* W4 = (const float4*)((m ? Wdst : Wsrc) + (size_t)k * D) + 4 * p;
    float acc = 0.f;
#pragma unroll
    for (int j = 0; j < 4; j++) {
        float4 w = __ldg(W4 + j);
        int e = 16 * p + 4 * j;
        acc = fmaf(w.x, __ldg(&Wcls[(e + 0) * C + c]), acc);
        acc = fmaf(w.y, __ldg(&Wcls[(e + 1) * C + c]), acc);
        acc = fmaf(w.z, __ldg(&Wcls[(e + 2) * C + c]), acc);
        acc = fmaf(w.w, __ldg(&Wcls[(e + 3) * C + c]), acc);
    }
    acc += __shfl_down_sync(0xffffffffu, acc, 4);
    acc += __shfl_down_sync(0xffffffffu, acc, 2);
    acc += __shfl_down_sync(0xffffffffu, acc, 1);
    if (p == 0)
        (m ? g_WdT : g_WsT)[c * CP + k] = acc;
}

// ---------------------------------------------------------------------------
// Per-node projection: warp = NPT nodes x (lane = class), f32x2 FMAs.
// Normal tables only (rotated tables removed with the abandoned R8 scheme).
// ---------------------------------------------------------------------------
__global__ void __launch_bounds__(256) nodeproj_kernel(const float* __restrict__ emb, int N) {
    __shared__ __align__(16) float sWs[C * CP];
    __shared__ __align__(16) float sWd[C * CP];
    __shared__ float sbc[C];
    for (int i = threadIdx.x; i < C * CP; i += blockDim.x) {
        sWs[i] = g_WsT[i];
        sWd[i] = g_WdT[i];
    }
    if (threadIdx.x < C) sbc[threadIdx.x] = g_bc[threadIdx.x];
    __syncthreads();

    int wid  = threadIdx.x >> 5;
    int lane = threadIdx.x & 31;
    int n0   = (blockIdx.x * 8 + wid) * NPT;
    if (n0 >= N) return;

    int cc = (lane < C) ? lane : (C - 1);
    const ulonglong2* ws2 = (const ulonglong2*)(sWs + cc * CP);
    const ulonglong2* wd2 = (const ulonglong2*)(sWd + cc * CP);
    const ulonglong2* e2  = (const ulonglong2*)(emb + (size_t)n0 * D);

    ull as2[NPT], ad2[NPT];
#pragma unroll
    for (int j = 0; j < NPT; j++) { as2[j] = 0ull; ad2[j] = 0ull; }

    int nv = N - n0; if (nv > NPT) nv = NPT;

    if (nv == NPT) {
#pragma unroll
        for (int k = 0; k < D / 4; k++) {
            ulonglong2 ws = ws2[k];
            ulonglong2 wd = wd2[k];
#pragma unroll
            for (int j = 0; j < NPT; j++) {
                ulonglong2 ev = __ldg(e2 + (size_t)j * (D / 4) + k);  // warp broadcast
                as2[j] = fma2(ev.x, ws.x, as2[j]);
                as2[j] = fma2(ev.y, ws.y, as2[j]);
                ad2[j] = fma2(ev.x, wd.x, ad2[j]);
                ad2[j] = fma2(ev.y, wd.y, ad2[j]);
            }
        }
    } else {
        for (int k = 0; k < D / 4; k++) {
            ulonglong2 ws = ws2[k];
            ulonglong2 wd = wd2[k];
            for (int j = 0; j < nv; j++) {
                ulonglong2 ev = __ldg(e2 + (size_t)j * (D / 4) + k);
                as2[j] = fma2(ev.x, ws.x, as2[j]);
                as2[j] = fma2(ev.y, ws.y, as2[j]);
                ad2[j] = fma2(ev.x, wd.x, ad2[j]);
                ad2[j] = fma2(ev.y, wd.y, ad2[j]);
            }
        }
    }

    if (lane < C) {
        float bc = sbc[lane];
#pragma unroll
        for (int j = 0; j < NPT; j++) {
            if (j < nv) {
                g_Ps[(size_t)(n0 + j) * PROW + lane] = f2sum(as2[j]) + bc;
                g_Pd[(size_t)(n0 + j) * PROW + lane] = f2sum(ad2[j]);
            }
        }
    }
}

// ---------------------------------------------------------------------------
// Edge kernel: exact R6 form (best measured). Half-warp cooperative, 2 edges
// per iteration:
//  - one coalesced 32-edge index load per warp
//  - each 16-lane half gathers one full P row per table via LDG.64
//  - packed f32x2 add; direct predicated evict-first STG.32 stores.
// This sits at the L2 sector-throughput bound (~284B/edge through LTS).
// ---------------------------------------------------------------------------
__global__ void __launch_bounds__(256) edge_kernel(const uint32_t* __restrict__ ew,
                                                   float* __restrict__ out,
                                                   uint32_t E) {
    const uint32_t F = 0xffffffffu;
    uint32_t wid  = threadIdx.x >> 5;
    uint32_t lane = threadIdx.x & 31;
    uint32_t warp = blockIdx.x * 8u + wid;
    uint32_t e0   = warp * 32u;
    if (e0 >= E) return;

    uint32_t myE = e0 + lane;
    bool have = (myE < E);
    uint32_t sv = 0, dv = 0;
    if (g_is64) {
        const uint2* ew2 = (const uint2*)ew;
        if (have) {
            sv = ew2[myE].x;
            dv = ew2[(size_t)E + myE].x;
        }
    } else {
        if (have) {
            sv = ew[myE];
            dv = ew[(size_t)E + myE];
        }
    }

    const ull* __restrict__ Ps8 = (const ull*)g_Ps;   // row = 16 ulls (128B)
    const ull* __restrict__ Pd8 = (const ull*)g_Pd;

    uint32_t h = lane >> 4;          // half id: edge parity within the pair
    uint32_t q = lane & 15;          // float-pair index within row
    uint32_t nIt = E - e0; if (nIt > 32u) nIt = 32u;

    if (nIt == 32u) {
#pragma unroll 8
        for (int it = 0; it < 16; ++it) {
            uint32_t eidx = 2u * (uint32_t)it + h;
            uint32_t s = __shfl_sync(F, sv, eidx);
            uint32_t d = __shfl_sync(F, dv, eidx);
            ull a = __ldg(Ps8 + (size_t)s * 16u + q);
            ull b = __ldg(Pd8 + (size_t)d * 16u + q);
            float lo, hi;
            unpack2(add2(a, b), lo, hi);
            float* base = out + (size_t)(e0 + eidx) * C;
            if (q <= 10u) __stcs(base + 2u * q, lo);        // floats 0,2,...,20
            if (q <= 9u)  __stcs(base + 2u * q + 1u, hi);   // floats 1,3,...,19
        }
    } else {
        const float* __restrict__ Ps = g_Ps;
        const float* __restrict__ Pd = g_Pd;
        for (uint32_t it = 0; it < nIt; ++it) {
            uint32_t s = __shfl_sync(F, sv, it);
            uint32_t d = __shfl_sync(F, dv, it);
            if (lane < C) {
                float v = __ldg(&Ps[(size_t)s * PROW + lane]) +
                          __ldg(&Pd[(size_t)d * PROW + lane]);
                out[(size_t)(e0 + it) * C + lane] = v;
            }
        }
    }
}

// ---------------------------------------------------------------------------
extern "C" void kernel_launch(void* const* d_in, const int* in_sizes, int n_in,
                              void* d_out, int out_size) {
    const float*    emb   = (const float*)d_in[0];
    const uint32_t* ei    = (const uint32_t*)d_in[1];
    const float*    Wsrc  = (const float*)d_in[2];
    const float*    Wdst  = (const float*)d_in[3];
    const float*    bfuse = (const float*)d_in[4];
    const float*    Wcls  = (const float*)d_in[5];
    const float*    bcls  = (const float*)d_in[6];
    float* out = (float*)d_out;

    int N = in_sizes[0] / D;          // 50000
    int E = in_sizes[1] / 2;          // 1600000

    int cblocks = (2 * D * C * 8) / 256 + 1;   // 168 compute + 1 detect/bias
    combine_kernel<<<cblocks, 256>>>(Wsrc, Wdst, Wcls, bfuse, bcls, ei);

    int nodesPerBlock = 8 * NPT;
    nodeproj_kernel<<<(N + nodesPerBlock - 1) / nodesPerBlock, 256>>>(emb, N);

    uint32_t warps  = ((uint32_t)E + 31u) / 32u;
    uint32_t blocks = (warps + 7u) / 8u;
    edge_kernel<<<blocks, 256>>>(ei, out, (uint32_t)E);
}

// round 12
// speedup vs baseline: 1.0914x; 1.0211x over previous
#include <cuda_runtime.h>
#include <cuda_fp16.h>
#include <cstdint>

#define D    128
#define C    21
#define HROW 32       // fp16 P-table row stride (halves) = 64B
#define MAXN 50000
#define NPT  8        // nodes per warp in nodeproj
#define CP   132

typedef unsigned long long ull;

// Scratch (static device globals — no allocation allowed)
__device__ float  g_WsT[C * CP];
__device__ float  g_WdT[C * CP];
__device__ float  g_bc[C];
__device__ __half g_PsH[MAXN * HROW];   // fp16 tables: 64B rows, 2 sectors/gather
__device__ __half g_PdH[MAXN * HROW];
__device__ int    g_is64;

// ---- packed fp32x2 ops (sm_103a; PTX-only forms) ---------------------------
__device__ __forceinline__ ull fma2(ull a, ull b, ull c) {
    ull d;
    asm("fma.rn.f32x2 %0, %1, %2, %3;" : "=l"(d) : "l"(a), "l"(b), "l"(c));
    return d;
}
__device__ __forceinline__ void unpack2(ull v, float& lo, float& hi) {
    uint32_t l, h;
    asm("mov.b64 {%0, %1}, %2;" : "=r"(l), "=r"(h) : "l"(v));
    lo = __uint_as_float(l); hi = __uint_as_float(h);
}
__device__ __forceinline__ float f2sum(ull v) {
    float lo, hi; unpack2(v, lo, hi); return lo + hi;
}

// ---------------------------------------------------------------------------
// combine_kernel: no smem/sync. 8 lanes per output, shfl-tree reduce.
// Last block: dtype detection + bias fold.
// ---------------------------------------------------------------------------
__global__ void __launch_bounds__(256) combine_kernel(const float* __restrict__ Wsrc,
                                                      const float* __restrict__ Wdst,
                                                      const float* __restrict__ Wcls,
                                                      const float* __restrict__ bfuse,
                                                      const float* __restrict__ bcls,
                                                      const uint32_t* __restrict__ ew) {
    if (blockIdx.x == gridDim.x - 1) {
        if (threadIdx.x < 32) {
            int lane = threadIdx.x;
            uint32_t v = 0;
#pragma unroll
            for (int i = 0; i < 8; i++)
                v |= ew[1 + 2 * (lane + 32 * i)];   // odd words: int64 high halves
#pragma unroll
            for (int o = 16; o; o >>= 1)
                v |= __shfl_xor_sync(0xffffffffu, v, o);
            if (lane == 0) g_is64 = (v == 0u) ? 1 : 0;
        } else if (threadIdx.x < 32 + C) {
            int c = threadIdx.x - 32;
            float acc = bcls[c];
#pragma unroll 8
            for (int j = 0; j < D; j++)
                acc = fmaf(__ldg(&bfuse[j]), __ldg(&Wcls[j * C + c]), acc);
            g_bc[c] = acc;
        }
        return;
    }

    int t = blockIdx.x * blockDim.x + threadIdx.x;
    int o = t >> 3;                                  // output id in [0, 2*D*C)
    int p = t & 7;                                   // eighth of K (16 elems)
    int m = o / (D * C);
    int r = o % (D * C);
    int k = r / C;
    int c = r % C;

    const float4* W4 = (const float4*)((m ? Wdst : Wsrc) + (size_t)k * D) + 4 * p;
    float acc = 0.f;
#pragma unroll
    for (int j = 0; j < 4; j++) {
        float4 w = __ldg(W4 + j);
        int e = 16 * p + 4 * j;
        acc = fmaf(w.x, __ldg(&Wcls[(e + 0) * C + c]), acc);
        acc = fmaf(w.y, __ldg(&Wcls[(e + 1) * C + c]), acc);
        acc = fmaf(w.z, __ldg(&Wcls[(e + 2) * C + c]), acc);
        acc = fmaf(w.w, __ldg(&Wcls[(e + 3) * C + c]), acc);
    }
    acc += __shfl_down_sync(0xffffffffu, acc, 4);
    acc += __shfl_down_sync(0xffffffffu, acc, 2);
    acc += __shfl_down_sync(0xffffffffu, acc, 1);
    if (p == 0)
        (m ? g_WdT : g_WsT)[c * CP + k] = acc;
}

// ---------------------------------------------------------------------------
// Per-node projection: warp = NPT nodes x (lane = class), f32x2 FMAs.
// Accumulates in fp32, stores fp16 table entries (halved gather traffic).
// ---------------------------------------------------------------------------
__global__ void __launch_bounds__(256) nodeproj_kernel(const float* __restrict__ emb, int N) {
    __shared__ __align__(16) float sWs[C * CP];
    __shared__ __align__(16) float sWd[C * CP];
    __shared__ float sbc[C];
    for (int i = threadIdx.x; i < C * CP; i += blockDim.x) {
        sWs[i] = g_WsT[i];
        sWd[i] = g_WdT[i];
    }
    if (threadIdx.x < C) sbc[threadIdx.x] = g_bc[threadIdx.x];
    __syncthreads();

    int wid  = threadIdx.x >> 5;
    int lane = threadIdx.x & 31;
    int n0   = (blockIdx.x * 8 + wid) * NPT;
    if (n0 >= N) return;

    int cc = (lane < C) ? lane : (C - 1);
    const ulonglong2* ws2 = (const ulonglong2*)(sWs + cc * CP);
    const ulonglong2* wd2 = (const ulonglong2*)(sWd + cc * CP);
    const ulonglong2* e2  = (const ulonglong2*)(emb + (size_t)n0 * D);

    ull as2[NPT], ad2[NPT];
#pragma unroll
    for (int j = 0; j < NPT; j++) { as2[j] = 0ull; ad2[j] = 0ull; }

    int nv = N - n0; if (nv > NPT) nv = NPT;

    if (nv == NPT) {
#pragma unroll
        for (int k = 0; k < D / 4; k++) {
            ulonglong2 ws = ws2[k];
            ulonglong2 wd = wd2[k];
#pragma unroll
            for (int j = 0; j < NPT; j++) {
                ulonglong2 ev = __ldg(e2 + (size_t)j * (D / 4) + k);  // warp broadcast
                as2[j] = fma2(ev.x, ws.x, as2[j]);
                as2[j] = fma2(ev.y, ws.y, as2[j]);
                ad2[j] = fma2(ev.x, wd.x, ad2[j]);
                ad2[j] = fma2(ev.y, wd.y, ad2[j]);
            }
        }
    } else {
        for (int k = 0; k < D / 4; k++) {
            ulonglong2 ws = ws2[k];
            ulonglong2 wd = wd2[k];
            for (int j = 0; j < nv; j++) {
                ulonglong2 ev = __ldg(e2 + (size_t)j * (D / 4) + k);
                as2[j] = fma2(ev.x, ws.x, as2[j]);
                as2[j] = fma2(ev.y, ws.y, as2[j]);
                ad2[j] = fma2(ev.x, wd.x, ad2[j]);
                ad2[j] = fma2(ev.y, wd.y, ad2[j]);
            }
        }
    }

    if (lane < C) {
        float bc = sbc[lane];
#pragma unroll
        for (int j = 0; j < NPT; j++) {
            if (j < nv) {
                size_t row = (size_t)(n0 + j) * HROW;
                g_PsH[row + lane] = __float2half_rn(f2sum(as2[j]) + bc);
                g_PdH[row + lane] = __float2half_rn(f2sum(ad2[j]));
            }
        }
    }
}

// ---------------------------------------------------------------------------
// Edge kernel: R6 form (measured best) with fp16 tables.
// Half-warp per edge, 2 edges per iteration:
//  - one coalesced 32-edge index load per warp
//  - lane q loads one uint32 = 2 halves of each table row (UNPREDICATED:
//    lanes 11..15 read in-row padding in an already-touched sector — free)
//  - fp16x2 -> float2 convert (ALU), fp32 add, predicated STG.32 stores.
// Per-edge LTS traffic: 2x64B reads + ~96B write + 8B index = 232B (was 296).
// ---------------------------------------------------------------------------
__global__ void __launch_bounds__(256) edge_kernel(const uint32_t* __restrict__ ew,
                                                   float* __restrict__ out,
                                                   uint32_t E) {
    const uint32_t F = 0xffffffffu;
    uint32_t wid  = threadIdx.x >> 5;
    uint32_t lane = threadIdx.x & 31;
    uint32_t warp = blockIdx.x * 8u + wid;
    uint32_t e0   = warp * 32u;
    if (e0 >= E) return;

    uint32_t myE = e0 + lane;
    bool have = (myE < E);
    uint32_t sv = 0, dv = 0;
    if (g_is64) {
        const uint2* ew2 = (const uint2*)ew;
        if (have) {
            sv = ew2[myE].x;
            dv = ew2[(size_t)E + myE].x;
        }
    } else {
        if (have) {
            sv = ew[myE];
            dv = ew[(size_t)E + myE];
        }
    }

    const uint32_t* __restrict__ PsU = (const uint32_t*)g_PsH;  // row = 16 uints (64B)
    const uint32_t* __restrict__ PdU = (const uint32_t*)g_PdH;

    uint32_t h = lane >> 4;          // half id: edge parity within the pair
    uint32_t q = lane & 15;          // half2 index within row
    uint32_t nIt = E - e0; if (nIt > 32u) nIt = 32u;

    if (nIt == 32u) {
#pragma unroll 8
        for (int it = 0; it < 16; ++it) {
            uint32_t eidx = 2u * (uint32_t)it + h;
            uint32_t s = __shfl_sync(F, sv, eidx);
            uint32_t d = __shfl_sync(F, dv, eidx);
            uint32_t a = __ldg(PsU + (size_t)s * 16u + q);   // in-row for all q
            uint32_t b = __ldg(PdU + (size_t)d * 16u + q);
            float2 fa = __half22float2(*(__half2*)&a);
            float2 fb = __half22float2(*(__half2*)&b);
            float lo = fa.x + fb.x;
            float hi = fa.y + fb.y;
            float* base = out + (size_t)(e0 + eidx) * C;
            if (q <= 10u) __stcs(base + 2u * q, lo);        // floats 0,2,...,20
            if (q <= 9u)  __stcs(base + 2u * q + 1u, hi);   // floats 1,3,...,19
        }
    } else {
        for (uint32_t it = 0; it < nIt; ++it) {
            uint32_t s = __shfl_sync(F, sv, it);
            uint32_t d = __shfl_sync(F, dv, it);
            if (lane < C) {
                float v = __half2float(g_PsH[(size_t)s * HROW + lane]) +
                          __half2float(g_PdH[(size_t)d * HROW + lane]);
                out[(size_t)(e0 + it) * C + lane] = v;
            }
        }
    }
}

// ---------------------------------------------------------------------------
extern "C" void kernel_launch(void* const* d_in, const int* in_sizes, int n_in,
                              void* d_out, int out_size) {
    const float*    emb   = (const float*)d_in[0];
    const uint32_t* ei    = (const uint32_t*)d_in[1];
    const float*    Wsrc  = (const float*)d_in[2];
    const float*    Wdst  = (const float*)d_in[3];
    const float*    bfuse = (const float*)d_in[4];
    const float*    Wcls  = (const float*)d_in[5];
    const float*    bcls  = (const float*)d_in[6];
    float* out = (float*)d_out;

    int N = in_sizes[0] / D;          // 50000
    int E = in_sizes[1] / 2;          // 1600000

    int cblocks = (2 * D * C * 8) / 256 + 1;   // 168 compute + 1 detect/bias
    combine_kernel<<<cblocks, 256>>>(Wsrc, Wdst, Wcls, bfuse, bcls, ei);

    int nodesPerBlock = 8 * NPT;
    nodeproj_kernel<<<(N + nodesPerBlock - 1) / nodesPerBlock, 256>>>(emb, N);

    uint32_t warps  = ((uint32_t)E + 31u) / 32u;
    uint32_t blocks = (warps + 7u) / 8u;
    edge_kernel<<<blocks, 256>>>(ei, out, (uint32_t)E);
}